// round 9
// baseline (speedup 1.0000x reference)
#include <cuda_runtime.h>

#define HDIM 2048
#define HH (HDIM * HDIM)
#define BINS 256
#define NTHREADS 256
#define NBLOCKS 888    // 148 SMs * 6 blocks — one fully-resident wave (<= 912 on 152-SM GB300)

// ---------------- scratch (static device globals; no allocation) -------------
// Per-pixel sample counts, byte-packed: 4 pixels per u32 word.
// Counts are Binomial(2e6, 1/4.19e6) -> P(count>=256) ~ 1e-600; u8 never overflows.
__device__ unsigned int g_cnt_src_w[HH / 4];
__device__ unsigned int g_cnt_tar_w[HH / 4];
__device__ unsigned int g_hist_dst[3 * BINS];
__device__ unsigned int g_hist_ref[3 * BINS];
__device__ double       g_loss;
__device__ unsigned int g_tick_loss;
__device__ unsigned int g_bar_count;   // barrier state: count self-resets, gen monotonic
__device__ unsigned int g_bar_gen;

// replicate JAX arithmetic exactly: ((x + 1) * 0.5) * 255   (no FMA contraction)
__device__ __forceinline__ float to_image255(float x) {
    return __fmul_rn(__fmul_rn(__fadd_rn(x, 1.0f), 0.5f), 255.0f);
}

__device__ __forceinline__ int bin_of(float v) {
    return min((int)v, BINS - 1);
}

// Sense-reversing grid barrier. Requires all blocks co-resident (one wave).
__device__ __forceinline__ void grid_barrier() {
    __syncthreads();
    if (threadIdx.x == 0) {
        __threadfence();
        volatile unsigned int* vgen = &g_bar_gen;
        unsigned int gen = *vgen;
        unsigned int t = atomicAdd(&g_bar_count, 1u);
        if (t == (unsigned int)(gridDim.x - 1)) {
            g_bar_count = 0u;          // all blocks arrived; safe to reset
            __threadfence();
            *vgen = gen + 1u;
        } else {
            while (*vgen == gen) __nanosleep(64);
        }
        __threadfence();
    }
    __syncthreads();
}

__device__ __forceinline__ void bump_u8(unsigned int* base, int p) {
    atomicAdd(&base[p >> 2], 1u << ((p & 3) * 8));
}

// =================== the whole pipeline in ONE persistent kernel =============
__global__ void __launch_bounds__(NTHREADS, 6)
k_fused(const float* __restrict__ inp,
        const float* __restrict__ tgtimg,
        const float* __restrict__ msrc,
        const float* __restrict__ mtar,
        const int* __restrict__ i0, const int* __restrict__ i1,
        const int* __restrict__ i2, const int* __restrict__ i3,
        const float* __restrict__ refimg,
        float* __restrict__ out, int n) {
    __shared__ unsigned int sh[6 * BINS];   // hist, later reused as float cdf
    __shared__ float sh_tab[3 * BINS];
    __shared__ double ws[NTHREADS / 32];

    const int tid = blockIdx.x * blockDim.x + threadIdx.x;
    const int stride = gridDim.x * blockDim.x;

    // ---------------- phase 1: zero scratch ----------------
    {
        uint4 z = make_uint4(0u, 0u, 0u, 0u);
        uint4* a = reinterpret_cast<uint4*>(g_cnt_src_w);
        uint4* b = reinterpret_cast<uint4*>(g_cnt_tar_w);
        for (int i = tid; i < HH / 16; i += stride) { a[i] = z; b[i] = z; }
        if (blockIdx.x == 0) {
            for (int i = threadIdx.x; i < 3 * BINS; i += blockDim.x) {
                g_hist_dst[i] = 0u;
                g_hist_ref[i] = 0u;
            }
            if (threadIdx.x == 0) { g_loss = 0.0; g_tick_loss = 0u; }
        }
    }
    grid_barrier();

    // ---------------- phase 2: per-pixel sample counts ----------------
    {
        int n4 = n >> 2;
        const int4* I0 = reinterpret_cast<const int4*>(i0);
        const int4* I1 = reinterpret_cast<const int4*>(i1);
        const int4* I2 = reinterpret_cast<const int4*>(i2);
        const int4* I3 = reinterpret_cast<const int4*>(i3);
        for (int k = tid; k < n4; k += stride) {
            int4 a = __ldcs(&I0[k]);   // read-once streams: evict-first
            int4 b = __ldcs(&I1[k]);
            int4 c = __ldcs(&I2[k]);
            int4 d = __ldcs(&I3[k]);
            bump_u8(g_cnt_src_w, a.x * HDIM + b.x);
            bump_u8(g_cnt_src_w, a.y * HDIM + b.y);
            bump_u8(g_cnt_src_w, a.z * HDIM + b.z);
            bump_u8(g_cnt_src_w, a.w * HDIM + b.w);
            bump_u8(g_cnt_tar_w, c.x * HDIM + d.x);
            bump_u8(g_cnt_tar_w, c.y * HDIM + d.y);
            bump_u8(g_cnt_tar_w, c.z * HDIM + d.z);
            bump_u8(g_cnt_tar_w, c.w * HDIM + d.w);
        }
        for (int k = (n4 << 2) + tid; k < n; k += stride) {
            bump_u8(g_cnt_src_w, i0[k] * HDIM + i1[k]);
            bump_u8(g_cnt_tar_w, i2[k] * HDIM + i3[k]);
        }
    }
    grid_barrier();

    // ---------------- phase 3: count-weighted histograms ----------------
    {
        for (int i = threadIdx.x; i < 6 * BINS; i += blockDim.x) sh[i] = 0u;
        __syncthreads();

        unsigned int z_s = 0u, z_t = 0u;   // masked-out mass -> bin 0

        const float4* MS = reinterpret_cast<const float4*>(msrc);
        const float4* MT = reinterpret_cast<const float4*>(mtar);
        const float4* R0 = reinterpret_cast<const float4*>(refimg);
        const float4* R1 = reinterpret_cast<const float4*>(refimg + HH);
        const float4* R2 = reinterpret_cast<const float4*>(refimg + 2 * HH);
        const float4* T0 = reinterpret_cast<const float4*>(tgtimg);
        const float4* T1 = reinterpret_cast<const float4*>(tgtimg + HH);
        const float4* T2 = reinterpret_cast<const float4*>(tgtimg + 2 * HH);

        for (int q = tid; q < HH / 4; q += stride) {
            unsigned int cw = __ldcg(&g_cnt_src_w[q]);
            if (cw) {
                float4 m = MS[q];
                unsigned int w0 = (m.x != 0.0f) ? (cw & 0xFFu) : 0u;
                unsigned int w1 = (m.y != 0.0f) ? ((cw >> 8) & 0xFFu) : 0u;
                unsigned int w2 = (m.z != 0.0f) ? ((cw >> 16) & 0xFFu) : 0u;
                unsigned int w3 = (m.w != 0.0f) ? (cw >> 24) : 0u;
                unsigned int tot = (cw & 0xFFu) + ((cw >> 8) & 0xFFu)
                                 + ((cw >> 16) & 0xFFu) + (cw >> 24);
                z_s += tot - (w0 + w1 + w2 + w3);
                if (w0 | w1 | w2 | w3) {
                    float4 p0 = R0[q], p1 = R1[q], p2 = R2[q];
                    if (w0) {
                        atomicAdd(&sh[0 * BINS + bin_of(to_image255(p0.x))], w0);
                        atomicAdd(&sh[1 * BINS + bin_of(to_image255(p1.x))], w0);
                        atomicAdd(&sh[2 * BINS + bin_of(to_image255(p2.x))], w0);
                    }
                    if (w1) {
                        atomicAdd(&sh[0 * BINS + bin_of(to_image255(p0.y))], w1);
                        atomicAdd(&sh[1 * BINS + bin_of(to_image255(p1.y))], w1);
                        atomicAdd(&sh[2 * BINS + bin_of(to_image255(p2.y))], w1);
                    }
                    if (w2) {
                        atomicAdd(&sh[0 * BINS + bin_of(to_image255(p0.z))], w2);
                        atomicAdd(&sh[1 * BINS + bin_of(to_image255(p1.z))], w2);
                        atomicAdd(&sh[2 * BINS + bin_of(to_image255(p2.z))], w2);
                    }
                    if (w3) {
                        atomicAdd(&sh[0 * BINS + bin_of(to_image255(p0.w))], w3);
                        atomicAdd(&sh[1 * BINS + bin_of(to_image255(p1.w))], w3);
                        atomicAdd(&sh[2 * BINS + bin_of(to_image255(p2.w))], w3);
                    }
                }
            }
            unsigned int tw = __ldcg(&g_cnt_tar_w[q]);
            if (tw) {
                float4 m = MT[q];
                unsigned int w0 = (m.x != 0.0f) ? (tw & 0xFFu) : 0u;
                unsigned int w1 = (m.y != 0.0f) ? ((tw >> 8) & 0xFFu) : 0u;
                unsigned int w2 = (m.z != 0.0f) ? ((tw >> 16) & 0xFFu) : 0u;
                unsigned int w3 = (m.w != 0.0f) ? (tw >> 24) : 0u;
                unsigned int tot = (tw & 0xFFu) + ((tw >> 8) & 0xFFu)
                                 + ((tw >> 16) & 0xFFu) + (tw >> 24);
                z_t += tot - (w0 + w1 + w2 + w3);
                if (w0 | w1 | w2 | w3) {
                    float4 p0 = T0[q], p1 = T1[q], p2 = T2[q];
                    if (w0) {
                        atomicAdd(&sh[3 * BINS + bin_of(to_image255(p0.x))], w0);
                        atomicAdd(&sh[4 * BINS + bin_of(to_image255(p1.x))], w0);
                        atomicAdd(&sh[5 * BINS + bin_of(to_image255(p2.x))], w0);
                    }
                    if (w1) {
                        atomicAdd(&sh[3 * BINS + bin_of(to_image255(p0.y))], w1);
                        atomicAdd(&sh[4 * BINS + bin_of(to_image255(p1.y))], w1);
                        atomicAdd(&sh[5 * BINS + bin_of(to_image255(p2.y))], w1);
                    }
                    if (w2) {
                        atomicAdd(&sh[3 * BINS + bin_of(to_image255(p0.z))], w2);
                        atomicAdd(&sh[4 * BINS + bin_of(to_image255(p1.z))], w2);
                        atomicAdd(&sh[5 * BINS + bin_of(to_image255(p2.z))], w2);
                    }
                    if (w3) {
                        atomicAdd(&sh[3 * BINS + bin_of(to_image255(p0.w))], w3);
                        atomicAdd(&sh[4 * BINS + bin_of(to_image255(p1.w))], w3);
                        atomicAdd(&sh[5 * BINS + bin_of(to_image255(p2.w))], w3);
                    }
                }
            }
        }

#pragma unroll
        for (int o = 16; o; o >>= 1) {
            z_s += __shfl_down_sync(0xffffffffu, z_s, o);
            z_t += __shfl_down_sync(0xffffffffu, z_t, o);
        }
        if ((threadIdx.x & 31) == 0) {
            if (z_s) {
                atomicAdd(&sh[0 * BINS], z_s);
                atomicAdd(&sh[1 * BINS], z_s);
                atomicAdd(&sh[2 * BINS], z_s);
            }
            if (z_t) {
                atomicAdd(&sh[3 * BINS], z_t);
                atomicAdd(&sh[4 * BINS], z_t);
                atomicAdd(&sh[5 * BINS], z_t);
            }
        }
        __syncthreads();

        for (int i = threadIdx.x; i < 3 * BINS; i += blockDim.x) {
            unsigned int hd = sh[i];
            unsigned int hr = sh[3 * BINS + i];
            if (hd) atomicAdd(&g_hist_dst[i], hd);
            if (hr) atomicAdd(&g_hist_ref[i], hr);
        }
    }
    grid_barrier();

    // -------- phase 4: EVERY block computes cdf + table into its own shared ---
    {
        float* cdf = reinterpret_cast<float*>(sh);
        int w = threadIdx.x >> 5, lane = threadIdx.x & 31;
        if (w < 6) {
            const unsigned int* h = (w < 3) ? &g_hist_dst[w * BINS]
                                            : &g_hist_ref[(w - 3) * BINS];
            unsigned int v[8];
            unsigned int s = 0u;
#pragma unroll
            for (int k = 0; k < 8; k++) { v[k] = __ldcg(&h[lane * 8 + k]); s += v[k]; }
            unsigned int pre = s;   // warp-inclusive scan (exact: ints < 2^24)
#pragma unroll
            for (int o = 1; o < 32; o <<= 1) {
                unsigned int t = __shfl_up_sync(0xffffffffu, pre, o);
                if (lane >= o) pre += t;
            }
            unsigned int total = __shfl_sync(0xffffffffu, pre, 31);
            unsigned int run = pre - s;
            float ftot = (float)total;
#pragma unroll
            for (int k = 0; k < 8; k++) {
                run += v[k];
                cdf[w * BINS + lane * 8 + k] = (float)run / ftot;  // same rounding as cumsum/sum
            }
        }
        __syncthreads();

        // monotone CDF => first matching interval = lower_bound(d in adj[1:]), valid iff adj[lo]<=d
        int i = threadIdx.x;
#pragma unroll
        for (int c = 0; c < 3; c++) {
            float outv;
            if (i == 0) {
                outv = 0.0f;
            } else if (i == BINS - 1) {
                outv = (float)(BINS - 1);
            } else {
                float d = cdf[c * BINS + i];
                const float* adj = &cdf[(3 + c) * BINS];
                int lo = 0, hi = BINS - 2;
                while (lo < hi) {
                    int mid = (lo + hi) >> 1;
                    if (adj[mid + 1] >= d) hi = mid; else lo = mid + 1;
                }
                outv = (adj[lo] <= d) ? (float)(lo + 1) : (float)i;
            }
            sh_tab[c * BINS + i] = outv;
        }
        __syncthreads();
    }

    // ---------------- phase 5: masked MSE + fused finalize ----------------
    {
        const float4* mp = reinterpret_cast<const float4*>(msrc);
        const float4* ip0 = reinterpret_cast<const float4*>(inp);
        const float4* ip1 = reinterpret_cast<const float4*>(inp + HH);
        const float4* ip2 = reinterpret_cast<const float4*>(inp + 2 * HH);
        const float4* rp0 = reinterpret_cast<const float4*>(refimg);
        const float4* rp1 = reinterpret_cast<const float4*>(refimg + HH);
        const float4* rp2 = reinterpret_cast<const float4*>(refimg + 2 * HH);

        float acc = 0.0f;
        for (int q = tid; q < HH / 4; q += stride) {
            float4 m4 = mp[q];
            unsigned int cw = __ldcg(&g_cnt_src_w[q]);
            float4 a0 = ip0[q], a1 = ip1[q], a2 = ip2[q];
            float4 b0 = rp0[q], b1 = rp1[q], b2 = rp2[q];

            float mm[4] = {m4.x, m4.y, m4.z, m4.w};
            float A[3][4] = {{a0.x, a0.y, a0.z, a0.w},
                             {a1.x, a1.y, a1.z, a1.w},
                             {a2.x, a2.y, a2.z, a2.w}};
            float Bv[3][4] = {{b0.x, b0.y, b0.z, b0.w},
                              {b1.x, b1.y, b1.z, b1.w},
                              {b2.x, b2.y, b2.z, b2.w}};
#pragma unroll
            for (int l = 0; l < 4; l++) {
                if (mm[l] != 0.0f) {
                    bool scat = ((cw >> (l * 8)) & 0xFFu) != 0u;
#pragma unroll
                    for (int c = 0; c < 3; c++) {
                        float rv = to_image255(Bv[c][l]);
                        float iv = to_image255(A[c][l]);
                        float mt = scat ? sh_tab[c * BINS + bin_of(rv)] : rv;
                        float d = iv - mt;
                        acc += d * d;
                    }
                }
            }
        }

#pragma unroll
        for (int o = 16; o; o >>= 1) acc += __shfl_down_sync(0xffffffffu, acc, o);
        if ((threadIdx.x & 31) == 0) ws[threadIdx.x >> 5] = (double)acc;
        __syncthreads();
        if (threadIdx.x == 0) {
            double s = 0.0;
            for (int w = 0; w < NTHREADS / 32; w++) s += ws[w];
            atomicAdd(&g_loss, s);
            __threadfence();
            unsigned int t = atomicAdd(&g_tick_loss, 1u);
            if (t == (unsigned int)(gridDim.x - 1)) {
                double L = atomicAdd(&g_loss, 0.0);  // coherent read of final sum
                out[0] = (float)(L / (double)(3.0 * (double)HH));
            }
        }
    }
}

// ---------------- launch ------------------------------------------------------
extern "C" void kernel_launch(void* const* d_in, const int* in_sizes, int n_in,
                              void* d_out, int out_size) {
    const float* input  = (const float*)d_in[0];
    const float* target = (const float*)d_in[1];
    const float* msrc   = (const float*)d_in[2];
    const float* mtar   = (const float*)d_in[3];
    const int*   i0     = (const int*)d_in[4];
    const int*   i1     = (const int*)d_in[5];
    const int*   i2     = (const int*)d_in[6];
    const int*   i3     = (const int*)d_in[7];
    const float* refimg = (const float*)d_in[8];
    float* out = (float*)d_out;
    int n = in_sizes[4];   // N samples

    k_fused<<<NBLOCKS, NTHREADS>>>(input, target, msrc, mtar,
                                   i0, i1, i2, i3, refimg, out, n);
}

// round 10
// speedup vs baseline: 1.0875x; 1.0875x over previous
#include <cuda_runtime.h>

#define HDIM 2048
#define HH (HDIM * HDIM)
#define BINS 256
#define NTHREADS 256
#define NBLOCKS 888    // ~one wave; grid-stride tolerates partial waves (no grid barriers)

// ---------------- scratch (static device globals; no allocation) -------------
// Per-pixel sample counts, byte-packed: 4 pixels per u32 word.
// Counts are Binomial(2e6, 1/4.19e6) -> P(count>=256) ~ 1e-600; u8 never overflows.
__device__ unsigned int g_cnt_src_w[HH / 4];
__device__ unsigned int g_cnt_tar_w[HH / 4];
__device__ unsigned int g_hist_dst[3 * BINS];
__device__ unsigned int g_hist_ref[3 * BINS];
// per-(channel,bin) moments over masked scat pixels: n, S1=sum(iv), S2=sum(iv^2)
__device__ unsigned int g_mom_n [3 * BINS];
__device__ double       g_mom_s1[3 * BINS];
__device__ double       g_mom_s2[3 * BINS];
__device__ double       g_loss;           // non-scat masked part, accumulated in sweep

// replicate JAX arithmetic exactly: ((x + 1) * 0.5) * 255   (no FMA contraction)
__device__ __forceinline__ float to_image255(float x) {
    return __fmul_rn(__fmul_rn(__fadd_rn(x, 1.0f), 0.5f), 255.0f);
}

__device__ __forceinline__ int bin_of(float v) {
    return min((int)v, BINS - 1);
}

// ---------------- K0: zero scratch ------------------------------------------
__global__ void k_zero() {
    int tid = blockIdx.x * blockDim.x + threadIdx.x;
    int stride = gridDim.x * blockDim.x;
    uint4 z = make_uint4(0u, 0u, 0u, 0u);
    uint4* a = reinterpret_cast<uint4*>(g_cnt_src_w);
    uint4* b = reinterpret_cast<uint4*>(g_cnt_tar_w);
    for (int i = tid; i < HH / 16; i += stride) { a[i] = z; b[i] = z; }
    if (blockIdx.x == 0) {
        for (int i = threadIdx.x; i < 3 * BINS; i += blockDim.x) {
            g_hist_dst[i] = 0u;
            g_hist_ref[i] = 0u;
            g_mom_n[i] = 0u;
            g_mom_s1[i] = 0.0;
            g_mom_s2[i] = 0.0;
        }
        if (threadIdx.x == 0) g_loss = 0.0;
    }
}

// ------- K1: per-pixel sample counts (int4 streaming loads, byte atomics) ----
__device__ __forceinline__ void bump_u8(unsigned int* base, int p) {
    atomicAdd(&base[p >> 2], 1u << ((p & 3) * 8));
}

__global__ void k_count(const int* __restrict__ i0, const int* __restrict__ i1,
                        const int* __restrict__ i2, const int* __restrict__ i3,
                        int n) {
    int tid = blockIdx.x * blockDim.x + threadIdx.x;
    int stride = gridDim.x * blockDim.x;
    int n4 = n >> 2;
    const int4* I0 = reinterpret_cast<const int4*>(i0);
    const int4* I1 = reinterpret_cast<const int4*>(i1);
    const int4* I2 = reinterpret_cast<const int4*>(i2);
    const int4* I3 = reinterpret_cast<const int4*>(i3);
    for (int k = tid; k < n4; k += stride) {
        int4 a = __ldcs(&I0[k]);   // read-once streams: evict-first
        int4 b = __ldcs(&I1[k]);
        int4 c = __ldcs(&I2[k]);
        int4 d = __ldcs(&I3[k]);
        bump_u8(g_cnt_src_w, a.x * HDIM + b.x);
        bump_u8(g_cnt_src_w, a.y * HDIM + b.y);
        bump_u8(g_cnt_src_w, a.z * HDIM + b.z);
        bump_u8(g_cnt_src_w, a.w * HDIM + b.w);
        bump_u8(g_cnt_tar_w, c.x * HDIM + d.x);
        bump_u8(g_cnt_tar_w, c.y * HDIM + d.y);
        bump_u8(g_cnt_tar_w, c.z * HDIM + d.z);
        bump_u8(g_cnt_tar_w, c.w * HDIM + d.w);
    }
    for (int k = (n4 << 2) + tid; k < n; k += stride) {
        bump_u8(g_cnt_src_w, i0[k] * HDIM + i1[k]);
        bump_u8(g_cnt_tar_w, i2[k] * HDIM + i3[k]);
    }
}

// ------- K2: ONE data sweep: histograms + per-bin loss moments ---------------
// Loss decomposition: for masked pixels,
//   count>0 (scat):  (iv - tab[b])^2, b=bin(rv)  -> accumulate n/S1/S2 per (c,b)
//   count==0:        (iv - rv)^2                 -> accumulate directly
// so the table is only needed over 768 bins, never over pixels.
__global__ void __launch_bounds__(NTHREADS)
k_sweep(const float* __restrict__ refimg,   // ref_data  (dst side, also in loss)
        const float* __restrict__ tgtimg,   // target_data (adj side)
        const float* __restrict__ inp,      // input_data (loss)
        const float* __restrict__ msrc,
        const float* __restrict__ mtar) {
    __shared__ unsigned int shh[6 * BINS];   // histograms (sample-weighted)
    __shared__ unsigned int shn[3 * BINS];   // moment n   (pixel-weighted)
    __shared__ float        s1 [3 * BINS];   // moment S1
    __shared__ float        s2 [3 * BINS];   // moment S2
    for (int i = threadIdx.x; i < 6 * BINS; i += blockDim.x) shh[i] = 0u;
    for (int i = threadIdx.x; i < 3 * BINS; i += blockDim.x) {
        shn[i] = 0u; s1[i] = 0.0f; s2[i] = 0.0f;
    }
    __syncthreads();

    unsigned int z_s = 0u, z_t = 0u;   // masked-out sample mass -> hist bin 0
    float acc = 0.0f;                  // non-scat masked loss

    const float4* MS = reinterpret_cast<const float4*>(msrc);
    const float4* MT = reinterpret_cast<const float4*>(mtar);
    const float4* R0 = reinterpret_cast<const float4*>(refimg);
    const float4* R1 = reinterpret_cast<const float4*>(refimg + HH);
    const float4* R2 = reinterpret_cast<const float4*>(refimg + 2 * HH);
    const float4* T0 = reinterpret_cast<const float4*>(tgtimg);
    const float4* T1 = reinterpret_cast<const float4*>(tgtimg + HH);
    const float4* T2 = reinterpret_cast<const float4*>(tgtimg + 2 * HH);
    const float4* A0 = reinterpret_cast<const float4*>(inp);
    const float4* A1 = reinterpret_cast<const float4*>(inp + HH);
    const float4* A2 = reinterpret_cast<const float4*>(inp + 2 * HH);

    int tid = blockIdx.x * blockDim.x + threadIdx.x;
    int stride = gridDim.x * blockDim.x;
    for (int q = tid; q < HH / 4; q += stride) {
        // ---------- dst side: hist_dst + loss moments ----------
        unsigned int cw = g_cnt_src_w[q];
        float4 m = MS[q];
        bool any_mask = (m.x != 0.0f) | (m.y != 0.0f) | (m.z != 0.0f) | (m.w != 0.0f);
        // masked-out sample mass -> bin 0
        if (cw) {
            unsigned int drop = 0u;
            if (m.x == 0.0f) drop += cw & 0xFFu;
            if (m.y == 0.0f) drop += (cw >> 8) & 0xFFu;
            if (m.z == 0.0f) drop += (cw >> 16) & 0xFFu;
            if (m.w == 0.0f) drop += cw >> 24;
            z_s += drop;
        }
        if (any_mask) {
            float4 p0 = R0[q], p1 = R1[q], p2 = R2[q];
            float4 a0 = A0[q], a1 = A1[q], a2 = A2[q];
            float mm[4] = {m.x, m.y, m.z, m.w};
            float Rv[3][4] = {{p0.x, p0.y, p0.z, p0.w},
                              {p1.x, p1.y, p1.z, p1.w},
                              {p2.x, p2.y, p2.z, p2.w}};
            float Av[3][4] = {{a0.x, a0.y, a0.z, a0.w},
                              {a1.x, a1.y, a1.z, a1.w},
                              {a2.x, a2.y, a2.z, a2.w}};
#pragma unroll
            for (int l = 0; l < 4; l++) {
                if (mm[l] != 0.0f) {
                    unsigned int cnt = (cw >> (l * 8)) & 0xFFu;
                    if (cnt) {
#pragma unroll
                        for (int c = 0; c < 3; c++) {
                            float rv = to_image255(Rv[c][l]);
                            float iv = to_image255(Av[c][l]);
                            int b = bin_of(rv);
                            atomicAdd(&shh[c * BINS + b], cnt);     // hist (sample weight)
                            atomicAdd(&shn[c * BINS + b], 1u);      // moments (pixel weight)
                            atomicAdd(&s1 [c * BINS + b], iv);
                            atomicAdd(&s2 [c * BINS + b], iv * iv);
                        }
                    } else {
#pragma unroll
                        for (int c = 0; c < 3; c++) {
                            float rv = to_image255(Rv[c][l]);
                            float iv = to_image255(Av[c][l]);
                            float d = iv - rv;
                            acc += d * d;
                        }
                    }
                }
            }
        }
        // ---------- adj side: hist_ref only ----------
        unsigned int tw = g_cnt_tar_w[q];
        if (tw) {
            float4 mt4 = MT[q];
            unsigned int w0 = (mt4.x != 0.0f) ? (tw & 0xFFu) : 0u;
            unsigned int w1 = (mt4.y != 0.0f) ? ((tw >> 8) & 0xFFu) : 0u;
            unsigned int w2 = (mt4.z != 0.0f) ? ((tw >> 16) & 0xFFu) : 0u;
            unsigned int w3 = (mt4.w != 0.0f) ? (tw >> 24) : 0u;
            unsigned int tot = (tw & 0xFFu) + ((tw >> 8) & 0xFFu)
                             + ((tw >> 16) & 0xFFu) + (tw >> 24);
            z_t += tot - (w0 + w1 + w2 + w3);
            if (w0 | w1 | w2 | w3) {
                float4 p0 = T0[q], p1 = T1[q], p2 = T2[q];
                if (w0) {
                    atomicAdd(&shh[3 * BINS + bin_of(to_image255(p0.x))], w0);
                    atomicAdd(&shh[4 * BINS + bin_of(to_image255(p1.x))], w0);
                    atomicAdd(&shh[5 * BINS + bin_of(to_image255(p2.x))], w0);
                }
                if (w1) {
                    atomicAdd(&shh[3 * BINS + bin_of(to_image255(p0.y))], w1);
                    atomicAdd(&shh[4 * BINS + bin_of(to_image255(p1.y))], w1);
                    atomicAdd(&shh[5 * BINS + bin_of(to_image255(p2.y))], w1);
                }
                if (w2) {
                    atomicAdd(&shh[3 * BINS + bin_of(to_image255(p0.z))], w2);
                    atomicAdd(&shh[4 * BINS + bin_of(to_image255(p1.z))], w2);
                    atomicAdd(&shh[5 * BINS + bin_of(to_image255(p2.z))], w2);
                }
                if (w3) {
                    atomicAdd(&shh[3 * BINS + bin_of(to_image255(p0.w))], w3);
                    atomicAdd(&shh[4 * BINS + bin_of(to_image255(p1.w))], w3);
                    atomicAdd(&shh[5 * BINS + bin_of(to_image255(p2.w))], w3);
                }
            }
        }
    }

    // bin-0 mass: warp-reduce then one shared atomic per warp
#pragma unroll
    for (int o = 16; o; o >>= 1) {
        z_s += __shfl_down_sync(0xffffffffu, z_s, o);
        z_t += __shfl_down_sync(0xffffffffu, z_t, o);
    }
    if ((threadIdx.x & 31) == 0) {
        if (z_s) {
            atomicAdd(&shh[0 * BINS], z_s);
            atomicAdd(&shh[1 * BINS], z_s);
            atomicAdd(&shh[2 * BINS], z_s);
        }
        if (z_t) {
            atomicAdd(&shh[3 * BINS], z_t);
            atomicAdd(&shh[4 * BINS], z_t);
            atomicAdd(&shh[5 * BINS], z_t);
        }
    }
    __syncthreads();

    // flush per-block hist + moments to global
    for (int i = threadIdx.x; i < 3 * BINS; i += blockDim.x) {
        unsigned int hd = shh[i];
        unsigned int hr = shh[3 * BINS + i];
        if (hd) atomicAdd(&g_hist_dst[i], hd);
        if (hr) atomicAdd(&g_hist_ref[i], hr);
        unsigned int nn = shn[i];
        if (nn) {
            atomicAdd(&g_mom_n[i], nn);
            atomicAdd(&g_mom_s1[i], (double)s1[i]);
            atomicAdd(&g_mom_s2[i], (double)s2[i]);
        }
    }

    // non-scat masked loss: warp reduce -> per-block double -> global
#pragma unroll
    for (int o = 16; o; o >>= 1) acc += __shfl_down_sync(0xffffffffu, acc, o);
    __shared__ double ws[NTHREADS / 32];
    if ((threadIdx.x & 31) == 0) ws[threadIdx.x >> 5] = (double)acc;
    __syncthreads();
    if (threadIdx.x == 0) {
        double s = 0.0;
        for (int w = 0; w < NTHREADS / 32; w++) s += ws[w];
        atomicAdd(&g_loss, s);
    }
}

// ------- K3: cdf + table over 768 bins, combine moments, finalize ------------
__global__ void k_final(float* __restrict__ out) {
    __shared__ float cdf[6 * BINS];
    __shared__ float tab[3 * BINS];
    __shared__ double part[BINS];
    int w = threadIdx.x >> 5, lane = threadIdx.x & 31;

    if (w < 6) {
        const unsigned int* h = (w < 3) ? &g_hist_dst[w * BINS]
                                        : &g_hist_ref[(w - 3) * BINS];
        unsigned int v[8];
        unsigned int s = 0u;
#pragma unroll
        for (int k = 0; k < 8; k++) { v[k] = __ldcg(&h[lane * 8 + k]); s += v[k]; }
        unsigned int pre = s;   // warp-inclusive scan (exact: ints < 2^24)
#pragma unroll
        for (int o = 1; o < 32; o <<= 1) {
            unsigned int t = __shfl_up_sync(0xffffffffu, pre, o);
            if (lane >= o) pre += t;
        }
        unsigned int total = __shfl_sync(0xffffffffu, pre, 31);
        unsigned int run = pre - s;
        float ftot = (float)total;
#pragma unroll
        for (int k = 0; k < 8; k++) {
            run += v[k];
            cdf[w * BINS + lane * 8 + k] = (float)run / ftot;  // same rounding as cumsum/sum
        }
    }
    __syncthreads();

    // monotone CDF => first matching interval = lower_bound(d in adj[1:]), valid iff adj[lo]<=d
    int i = threadIdx.x;
#pragma unroll
    for (int c = 0; c < 3; c++) {
        float outv;
        if (i == 0) {
            outv = 0.0f;
        } else if (i == BINS - 1) {
            outv = (float)(BINS - 1);
        } else {
            float d = cdf[c * BINS + i];
            const float* adj = &cdf[(3 + c) * BINS];
            int lo = 0, hi = BINS - 2;
            while (lo < hi) {
                int mid = (lo + hi) >> 1;
                if (adj[mid + 1] >= d) hi = mid; else lo = mid + 1;
            }
            outv = (adj[lo] <= d) ? (float)(lo + 1) : (float)i;
        }
        tab[c * BINS + i] = outv;
    }
    __syncthreads();

    // scat loss = sum over (c,b): S2 - 2*tab*S1 + n*tab^2
    double p = 0.0;
#pragma unroll
    for (int c = 0; c < 3; c++) {
        int idx = c * BINS + i;
        double t = (double)tab[idx];
        double nn = (double)__ldcg(&g_mom_n[idx]);
        if (nn != 0.0)
            p += g_mom_s2[idx] - 2.0 * t * g_mom_s1[idx] + nn * t * t;
    }
    part[i] = p;
    __syncthreads();
    // tree-reduce 256 doubles
    for (int o = BINS / 2; o > 0; o >>= 1) {
        if (i < o) part[i] += part[i + o];
        __syncthreads();
    }
    if (i == 0)
        out[0] = (float)((g_loss + part[0]) / (double)(3.0 * (double)HH));
}

// ---------------- launch ------------------------------------------------------
extern "C" void kernel_launch(void* const* d_in, const int* in_sizes, int n_in,
                              void* d_out, int out_size) {
    const float* input  = (const float*)d_in[0];
    const float* target = (const float*)d_in[1];
    const float* msrc   = (const float*)d_in[2];
    const float* mtar   = (const float*)d_in[3];
    const int*   i0     = (const int*)d_in[4];
    const int*   i1     = (const int*)d_in[5];
    const int*   i2     = (const int*)d_in[6];
    const int*   i3     = (const int*)d_in[7];
    const float* refimg = (const float*)d_in[8];
    float* out = (float*)d_out;
    int n = in_sizes[4];   // N samples

    k_zero <<<NBLOCKS, NTHREADS>>>();
    k_count<<<NBLOCKS, NTHREADS>>>(i0, i1, i2, i3, n);
    k_sweep<<<NBLOCKS, NTHREADS>>>(refimg, target, input, msrc, mtar);
    k_final<<<1, BINS>>>(out);
}